// round 1
// baseline (speedup 1.0000x reference)
#include <cuda_runtime.h>
#include <cuda_bf16.h>

// ---------------------------------------------------------------------------
// Problem shapes (fixed by the reference):
//   x:      [16, 4096, 512]  (M = 65536 rows, C = 512)
//   qkv_w:  [1536, 512]      -> qkv = x @ qkv_w^T          (NT GEMM)
//   attn:   1024 windows x 8 heads, each 64x64x64
//   proj_w: [512, 512], proj_b[512] -> out = a @ proj_w^T + b
// ---------------------------------------------------------------------------

#define M_ROWS   65536
#define C_DIM    512
#define QKV_DIM  1536
#define NH       8
#define HD       64
#define WINW     64
#define NWIN     1024

// Scratch (static device memory: allowed; runtime allocation is not)
__device__ float g_qkv[(long long)M_ROWS * QKV_DIM]; // 402 MB
__device__ float g_att[(long long)M_ROWS * C_DIM];   // 134 MB

// ---------------------------------------------------------------------------
// Tiled SGEMM (NT): C[m,n] = sum_k A[m*K+k] * B[n*K+k] (+ bias[n])
// BM=BN=128, BK=16, 256 threads, 8x8 microtile per thread.
// ---------------------------------------------------------------------------
__global__ __launch_bounds__(256, 2)
void sgemm_nt(const float* __restrict__ A, const float* __restrict__ B,
              const float* __restrict__ bias, float* __restrict__ C,
              int M, int N, int K)
{
    __shared__ float As[16][132];  // +4 pad: cheap conflict reduction on transposed stores
    __shared__ float Bs[16][132];

    const int tid = threadIdx.x;
    const long long m0 = (long long)blockIdx.y * 128;
    const int n0 = blockIdx.x * 128;

    const int rr = (tid >> 4) << 3;   // 0..120 step 8 (row of microtile)
    const int cc = (tid & 15) << 3;   // 0..120 step 8 (col of microtile)

    const int lr = tid >> 2;          // 0..63  (load row)
    const int lc = (tid & 3) << 2;    // 0,4,8,12 (load k-offset, float4)

    const float* Ab = A + (m0 + lr) * K + lc;
    const float* Bb = B + (long long)(n0 + lr) * K + lc;

    float acc[8][8];
#pragma unroll
    for (int i = 0; i < 8; i++)
#pragma unroll
        for (int j = 0; j < 8; j++) acc[i][j] = 0.f;

    // prefetch first tile
    float4 pa0 = *(const float4*)(Ab);
    float4 pa1 = *(const float4*)(Ab + 64 * K);
    float4 pb0 = *(const float4*)(Bb);
    float4 pb1 = *(const float4*)(Bb + 64 * K);

    for (int k0 = 0; k0 < K; k0 += 16) {
        __syncthreads();
        As[lc + 0][lr] = pa0.x; As[lc + 1][lr] = pa0.y;
        As[lc + 2][lr] = pa0.z; As[lc + 3][lr] = pa0.w;
        As[lc + 0][lr + 64] = pa1.x; As[lc + 1][lr + 64] = pa1.y;
        As[lc + 2][lr + 64] = pa1.z; As[lc + 3][lr + 64] = pa1.w;
        Bs[lc + 0][lr] = pb0.x; Bs[lc + 1][lr] = pb0.y;
        Bs[lc + 2][lr] = pb0.z; Bs[lc + 3][lr] = pb0.w;
        Bs[lc + 0][lr + 64] = pb1.x; Bs[lc + 1][lr + 64] = pb1.y;
        Bs[lc + 2][lr + 64] = pb1.z; Bs[lc + 3][lr + 64] = pb1.w;
        __syncthreads();

        if (k0 + 16 < K) {   // prefetch next tile (overlap with compute)
            pa0 = *(const float4*)(Ab + k0 + 16);
            pa1 = *(const float4*)(Ab + 64 * K + k0 + 16);
            pb0 = *(const float4*)(Bb + k0 + 16);
            pb1 = *(const float4*)(Bb + 64 * K + k0 + 16);
        }

#pragma unroll
        for (int k = 0; k < 16; k++) {
            float a[8], b[8];
            *(float4*)(a)     = *(const float4*)&As[k][rr];
            *(float4*)(a + 4) = *(const float4*)&As[k][rr + 4];
            *(float4*)(b)     = *(const float4*)&Bs[k][cc];
            *(float4*)(b + 4) = *(const float4*)&Bs[k][cc + 4];
#pragma unroll
            for (int i = 0; i < 8; i++)
#pragma unroll
                for (int j = 0; j < 8; j++)
                    acc[i][j] += a[i] * b[j];
        }
    }

    float bv[8];
#pragma unroll
    for (int j = 0; j < 8; j++) bv[j] = bias ? bias[n0 + cc + j] : 0.f;

#pragma unroll
    for (int i = 0; i < 8; i++) {
        float* Cp = C + (m0 + rr + i) * N + n0 + cc;
        float4 o0, o1;
        o0.x = acc[i][0] + bv[0]; o0.y = acc[i][1] + bv[1];
        o0.z = acc[i][2] + bv[2]; o0.w = acc[i][3] + bv[3];
        o1.x = acc[i][4] + bv[4]; o1.y = acc[i][5] + bv[5];
        o1.z = acc[i][6] + bv[6]; o1.w = acc[i][7] + bv[7];
        *(float4*)(Cp)     = o0;
        *(float4*)(Cp + 4) = o1;
    }
}

// ---------------------------------------------------------------------------
// Windowed attention: one CTA per (window, head). 64 threads in an 8x8 grid,
// each thread owns an 8x8 register tile of S (then of O). S stored transposed
// (St[k][q]) so both phases read smem broadcast/conflict-free.
// smem: qt(64x65) | kt(64x65) | v(64x64) | inv(64)   (St overlays qt)
// ---------------------------------------------------------------------------
__global__ __launch_bounds__(64)
void attn64(const float* __restrict__ qkv, float* __restrict__ out)
{
    extern __shared__ float sm[];
    float* qt  = sm;            // 4160 floats (stride 65), later St (stride 64)
    float* kt  = sm + 4160;     // 4160 floats (stride 65)
    float* vs  = sm + 8320;     // 4096 floats (stride 64)
    float* inv = sm + 12416;    // 64 floats

    const int tid = threadIdx.x;
    const int h  = blockIdx.x;
    const int wb = blockIdx.y;

    const float* base = qkv + (long long)wb * WINW * QKV_DIM + h * HD;

    // load q,k (transposed, padded) and v (row-major) — float4 from global
    for (int idx = tid; idx < 1024; idx += 64) {
        int w = idx >> 4;
        int e = (idx & 15) << 2;
        const float* p = base + (long long)w * QKV_DIM + e;
        float4 q4 = *(const float4*)(p);
        float4 k4 = *(const float4*)(p + 512);
        float4 v4 = *(const float4*)(p + 1024);
        qt[(e + 0) * 65 + w] = q4.x; qt[(e + 1) * 65 + w] = q4.y;
        qt[(e + 2) * 65 + w] = q4.z; qt[(e + 3) * 65 + w] = q4.w;
        kt[(e + 0) * 65 + w] = k4.x; kt[(e + 1) * 65 + w] = k4.y;
        kt[(e + 2) * 65 + w] = k4.z; kt[(e + 3) * 65 + w] = k4.w;
        *(float4*)&vs[w * 64 + e] = v4;
    }
    __syncthreads();

    const int rr = (tid >> 3) << 3;  // query rows of this thread's tile
    const int cc = (tid & 7) << 3;   // key cols of this thread's tile

    // Phase 1: S = Q K^T  (8x8 register tile per thread)
    float s[8][8];
#pragma unroll
    for (int i = 0; i < 8; i++)
#pragma unroll
        for (int j = 0; j < 8; j++) s[i][j] = 0.f;

#pragma unroll 4
    for (int e = 0; e < 64; e++) {
        float a[8], b[8];
#pragma unroll
        for (int i = 0; i < 8; i++) a[i] = qt[e * 65 + rr + i];
#pragma unroll
        for (int j = 0; j < 8; j++) b[j] = kt[e * 65 + cc + j];
#pragma unroll
        for (int i = 0; i < 8; i++)
#pragma unroll
            for (int j = 0; j < 8; j++)
                s[i][j] += a[i] * b[j];
    }
    __syncthreads();   // everyone done reading qt before we overwrite it

    // Write S^T (scaled) into qt region: St[k][q], stride 64
    float* St = qt;
#pragma unroll
    for (int i = 0; i < 8; i++)
#pragma unroll
        for (int j = 0; j < 8; j++)
            St[(cc + j) * 64 + rr + i] = s[i][j] * 0.125f;  // scale = hd^-0.5
    __syncthreads();

    // Softmax: thread tid handles query row r = tid (reads column r of St)
    {
        int r = tid;
        float mx = -1e30f;
#pragma unroll 8
        for (int j = 0; j < 64; j++) mx = fmaxf(mx, St[j * 64 + r]);
        float sum = 0.f;
#pragma unroll 8
        for (int j = 0; j < 64; j++) {
            float p = __expf(St[j * 64 + r] - mx);
            St[j * 64 + r] = p;
            sum += p;
        }
        inv[r] = 1.0f / sum;
    }
    __syncthreads();

    // Phase 2: O = P V  (8x8 register tile: rows = queries, cols = hd dims)
    float o[8][8];
#pragma unroll
    for (int i = 0; i < 8; i++)
#pragma unroll
        for (int j = 0; j < 8; j++) o[i][j] = 0.f;

#pragma unroll 4
    for (int j = 0; j < 64; j++) {
        float p[8], b[8];
#pragma unroll
        for (int i = 0; i < 8; i++) p[i] = St[j * 64 + rr + i];
        *(float4*)(b)     = *(const float4*)&vs[j * 64 + cc];
        *(float4*)(b + 4) = *(const float4*)&vs[j * 64 + cc + 4];
#pragma unroll
        for (int i = 0; i < 8; i++)
#pragma unroll
            for (int jj = 0; jj < 8; jj++)
                o[i][jj] += p[i] * b[jj];
    }

    // Epilogue: normalize rows and store to [n, c] scratch for the projection
#pragma unroll
    for (int i = 0; i < 8; i++) {
        float sc = inv[rr + i];
        float* op = out + ((long long)wb * WINW + rr + i) * C_DIM + h * HD + cc;
        float4 t0, t1;
        t0.x = o[i][0] * sc; t0.y = o[i][1] * sc;
        t0.z = o[i][2] * sc; t0.w = o[i][3] * sc;
        t1.x = o[i][4] * sc; t1.y = o[i][5] * sc;
        t1.z = o[i][6] * sc; t1.w = o[i][7] * sc;
        *(float4*)(op)     = t0;
        *(float4*)(op + 4) = t1;
    }
}

// ---------------------------------------------------------------------------
extern "C" void kernel_launch(void* const* d_in, const int* in_sizes, int n_in,
                              void* d_out, int out_size)
{
    const float* x      = (const float*)d_in[0];
    const float* qkv_w  = (const float*)d_in[1];
    const float* proj_w = (const float*)d_in[2];
    const float* proj_b = (const float*)d_in[3];
    float* out = (float*)d_out;

    float* qkv_buf = nullptr;
    float* att_buf = nullptr;
    cudaGetSymbolAddress((void**)&qkv_buf, g_qkv);
    cudaGetSymbolAddress((void**)&att_buf, g_att);

    const int attn_smem = 12480 * sizeof(float);   // 49920 B
    cudaFuncSetAttribute(attn64, cudaFuncAttributeMaxDynamicSharedMemorySize,
                         attn_smem);

    // 1) QKV projection: [65536,512] x [1536,512]^T -> [65536,1536]
    sgemm_nt<<<dim3(QKV_DIM / 128, M_ROWS / 128), 256>>>(
        x, qkv_w, nullptr, qkv_buf, M_ROWS, QKV_DIM, C_DIM);

    // 2) Windowed attention: 1024 windows x 8 heads
    attn64<<<dim3(NH, NWIN), 64, attn_smem>>>(qkv_buf, att_buf);

    // 3) Output projection: [65536,512] x [512,512]^T + bias -> [65536,512]
    sgemm_nt<<<dim3(C_DIM / 128, M_ROWS / 128), 256>>>(
        att_buf, proj_w, proj_b, out, M_ROWS, C_DIM, C_DIM);
}

// round 3
// speedup vs baseline: 2.0120x; 2.0120x over previous
#include <cuda_runtime.h>
#include <cuda_bf16.h>
#include <cstdint>

// ---------------------------------------------------------------------------
// Shapes: x[65536,512]; qkv_w[1536,512]; proj_w[512,512]; proj_b[512]
//   qkv = x @ qkv_w^T ; windowed attention (1024 win x 8 heads, 64x64x64);
//   out = att @ proj_w^T + b
// GEMMs: warp-level HMMA (mma.sync bf16) with 3-term hi/lo split for fp32
// accuracy. (tcgen05 PTX is rejected by this toolchain's sm_103 PTX target.)
// ---------------------------------------------------------------------------

#define M_ROWS   65536
#define C_DIM    512
#define QKV_DIM  1536
#define NH       8
#define HD       64
#define WINW     64
#define NWIN     1024

__device__ float g_qkv[(long long)M_ROWS * QKV_DIM]; // 402 MB scratch
__device__ float g_att[(long long)M_ROWS * C_DIM];   // 134 MB scratch

// ------------------------------ helpers ------------------------------------
__device__ __forceinline__ uint32_t smem_u32(const void* p) {
    uint32_t a;
    asm("{ .reg .u64 t; cvta.to.shared.u64 t, %1; cvt.u32.u64 %0, t; }"
        : "=r"(a) : "l"(p));
    return a;
}
__device__ __forceinline__ void ldsm4(uint32_t addr, uint32_t r[4]) {
    asm volatile("ldmatrix.sync.aligned.m8n8.x4.shared.b16 {%0,%1,%2,%3}, [%4];"
                 : "=r"(r[0]), "=r"(r[1]), "=r"(r[2]), "=r"(r[3]) : "r"(addr));
}
__device__ __forceinline__ void mma16816(float d[4], const uint32_t a[4],
                                         const uint32_t b0, const uint32_t b1) {
    asm volatile(
        "mma.sync.aligned.m16n8k16.row.col.f32.bf16.bf16.f32 "
        "{%0,%1,%2,%3},{%4,%5,%6,%7},{%8,%9},{%0,%1,%2,%3};"
        : "+f"(d[0]), "+f"(d[1]), "+f"(d[2]), "+f"(d[3])
        : "r"(a[0]), "r"(a[1]), "r"(a[2]), "r"(a[3]), "r"(b0), "r"(b1));
}
__device__ __forceinline__ uint32_t pack2(__nv_bfloat16 a, __nv_bfloat16 b) {
    return ((uint32_t)__bfloat16_as_ushort(b) << 16) | __bfloat16_as_ushort(a);
}

// Convert 8 consecutive fp32 -> 16B hi chunk + 16B lo chunk (bf16 split)
__device__ __forceinline__ void cvt8(const float* __restrict__ p,
                                     char* hi, char* lo, uint32_t off) {
    float4 v0 = *(const float4*)(p);
    float4 v1 = *(const float4*)(p + 4);
    float f[8] = {v0.x, v0.y, v0.z, v0.w, v1.x, v1.y, v1.z, v1.w};
    uint32_t H[4], L[4];
#pragma unroll
    for (int i = 0; i < 4; i++) {
        __nv_bfloat16 h0 = __float2bfloat16(f[2 * i]);
        __nv_bfloat16 h1 = __float2bfloat16(f[2 * i + 1]);
        __nv_bfloat16 l0 = __float2bfloat16(f[2 * i]     - __bfloat162float(h0));
        __nv_bfloat16 l1 = __float2bfloat16(f[2 * i + 1] - __bfloat162float(h1));
        H[i] = pack2(h0, h1);
        L[i] = pack2(l0, l1);
    }
    *(uint4*)(hi + off) = make_uint4(H[0], H[1], H[2], H[3]);
    *(uint4*)(lo + off) = make_uint4(L[0], L[1], L[2], L[3]);
}

// ---------------------------------------------------------------------------
// HMMA GEMM (NT): C[m,n] = sum_k A[m,k]*B[n,k] (+bias). fp32 in/out.
// CTA tile 128x128, BK=64. smem tiles: 128 rows x 128B (xor-swizzled chunks).
// 8 warps = 4(M) x 2(N); warp tile 32x64.
// ---------------------------------------------------------------------------
#define TB 16384   // bytes per bf16 tile (128 x 64 x 2)

__global__ __launch_bounds__(256, 2)
void gemm_hmma(const float* __restrict__ A, const float* __restrict__ B,
               const float* __restrict__ bias, float* __restrict__ C,
               int M, int N, int K)
{
    extern __shared__ char sm[];
    char* As_h = sm;
    char* As_l = sm + TB;
    char* Bs_h = sm + 2 * TB;
    char* Bs_l = sm + 3 * TB;
    const uint32_t sb = smem_u32(sm);

    const int tid  = threadIdx.x;
    const int lane = tid & 31;
    const int wid  = tid >> 5;
    const int wm   = wid & 3;    // M sub-block (32 rows)
    const int wn   = wid >> 2;   // N sub-block (64 cols)
    const long long m0 = (long long)blockIdx.y * 128;
    const int n0 = blockIdx.x * 128;

    float acc[2][8][4];
#pragma unroll
    for (int i = 0; i < 2; i++)
#pragma unroll
        for (int j = 0; j < 8; j++)
#pragma unroll
            for (int l = 0; l < 4; l++) acc[i][j][l] = 0.f;

    // per-lane ldmatrix row/chunk components
    const int arow0 = wm * 32 + (lane & 7) + ((lane >> 3) & 1) * 8;
    const int ac    = lane >> 4;          // A: chunk half from lane group
    const int brow0 = wn * 64 + (lane & 7) + (lane >> 4) * 8;
    const int bc    = (lane >> 3) & 1;    // B: chunk half from lane group

    const int NCH = K >> 6;
    for (int ch = 0; ch < NCH; ch++) {
        __syncthreads();
        // ---- convert this K-chunk of A and B into split bf16 smem tiles ----
#pragma unroll
        for (int i = 0; i < 4; i++) {
            int idx = tid + i * 256;          // 0..1023
            int row = idx >> 3;
            int c   = idx & 7;
            uint32_t off = (uint32_t)(row * 128 + ((c ^ (row & 7)) << 4));
            cvt8(A + (m0 + row) * K + ch * 64 + c * 8, As_h, As_l, off);
            cvt8(B + (long long)(n0 + row) * K + ch * 64 + c * 8, Bs_h, Bs_l, off);
        }
        __syncthreads();

        // ---- consume: 4 k16-steps per chunk ----
#pragma unroll
        for (int kk = 0; kk < 4; kk++) {
            uint32_t ah[2][4], al[2][4];
#pragma unroll
            for (int mt = 0; mt < 2; mt++) {
                int r = arow0 + mt * 16;
                uint32_t off = (uint32_t)(r * 128 + (((2 * kk + ac) ^ (r & 7)) << 4));
                ldsm4(sb + off, ah[mt]);
                ldsm4(sb + TB + off, al[mt]);
            }
#pragma unroll
            for (int nt = 0; nt < 4; nt++) {
                int r = brow0 + nt * 16;
                uint32_t off = (uint32_t)(r * 128 + (((2 * kk + bc) ^ (r & 7)) << 4));
                uint32_t bh[4], bl[4];
                ldsm4(sb + 2 * TB + off, bh);
                ldsm4(sb + 3 * TB + off, bl);
#pragma unroll
                for (int mt = 0; mt < 2; mt++) {
                    mma16816(acc[mt][nt * 2],     ah[mt], bh[0], bh[1]);
                    mma16816(acc[mt][nt * 2 + 1], ah[mt], bh[2], bh[3]);
                    mma16816(acc[mt][nt * 2],     ah[mt], bl[0], bl[1]);
                    mma16816(acc[mt][nt * 2 + 1], ah[mt], bl[2], bl[3]);
                    mma16816(acc[mt][nt * 2],     al[mt], bh[0], bh[1]);
                    mma16816(acc[mt][nt * 2 + 1], al[mt], bh[2], bh[3]);
                }
            }
        }
    }

    // ---- epilogue: fp32 stores (+bias) ----
    const int erow = lane >> 2;            // 0..7
    const int ecol = (lane & 3) * 2;       // 0,2,4,6
#pragma unroll
    for (int mt = 0; mt < 2; mt++) {
#pragma unroll
        for (int nt8 = 0; nt8 < 8; nt8++) {
            long long row = m0 + wm * 32 + mt * 16 + erow;
            int col = n0 + wn * 64 + nt8 * 8 + ecol;
            float b0 = bias ? bias[col]     : 0.f;
            float b1 = bias ? bias[col + 1] : 0.f;
            float2 r0 = make_float2(acc[mt][nt8][0] + b0, acc[mt][nt8][1] + b1);
            float2 r1 = make_float2(acc[mt][nt8][2] + b0, acc[mt][nt8][3] + b1);
            *(float2*)(C + row * N + col)       = r0;
            *(float2*)(C + (row + 8) * N + col) = r1;
        }
    }
}

// ---------------------------------------------------------------------------
// Windowed attention: one CTA per (window, head). (unchanged, fp32)
// ---------------------------------------------------------------------------
__global__ __launch_bounds__(64)
void attn64(const float* __restrict__ qkv, float* __restrict__ out)
{
    extern __shared__ float smf[];
    float* qt  = smf;
    float* kt  = smf + 4160;
    float* vs  = smf + 8320;
    float* inv = smf + 12416;

    const int tid = threadIdx.x;
    const int h  = blockIdx.x;
    const int wb = blockIdx.y;

    const float* base = qkv + (long long)wb * WINW * QKV_DIM + h * HD;

    for (int idx = tid; idx < 1024; idx += 64) {
        int w = idx >> 4;
        int e = (idx & 15) << 2;
        const float* p = base + (long long)w * QKV_DIM + e;
        float4 q4 = *(const float4*)(p);
        float4 k4 = *(const float4*)(p + 512);
        float4 v4 = *(const float4*)(p + 1024);
        qt[(e + 0) * 65 + w] = q4.x; qt[(e + 1) * 65 + w] = q4.y;
        qt[(e + 2) * 65 + w] = q4.z; qt[(e + 3) * 65 + w] = q4.w;
        kt[(e + 0) * 65 + w] = k4.x; kt[(e + 1) * 65 + w] = k4.y;
        kt[(e + 2) * 65 + w] = k4.z; kt[(e + 3) * 65 + w] = k4.w;
        *(float4*)&vs[w * 64 + e] = v4;
    }
    __syncthreads();

    const int rr = (tid >> 3) << 3;
    const int cc = (tid & 7) << 3;

    float s[8][8];
#pragma unroll
    for (int i = 0; i < 8; i++)
#pragma unroll
        for (int j = 0; j < 8; j++) s[i][j] = 0.f;

#pragma unroll 4
    for (int e = 0; e < 64; e++) {
        float a[8], b[8];
#pragma unroll
        for (int i = 0; i < 8; i++) a[i] = qt[e * 65 + rr + i];
#pragma unroll
        for (int j = 0; j < 8; j++) b[j] = kt[e * 65 + cc + j];
#pragma unroll
        for (int i = 0; i < 8; i++)
#pragma unroll
            for (int j = 0; j < 8; j++)
                s[i][j] += a[i] * b[j];
    }
    __syncthreads();

    float* St = qt;
#pragma unroll
    for (int i = 0; i < 8; i++)
#pragma unroll
        for (int j = 0; j < 8; j++)
            St[(cc + j) * 64 + rr + i] = s[i][j] * 0.125f;
    __syncthreads();

    {
        int r = tid;
        float mx = -1e30f;
#pragma unroll 8
        for (int j = 0; j < 64; j++) mx = fmaxf(mx, St[j * 64 + r]);
        float sum = 0.f;
#pragma unroll 8
        for (int j = 0; j < 64; j++) {
            float p = __expf(St[j * 64 + r] - mx);
            St[j * 64 + r] = p;
            sum += p;
        }
        inv[r] = 1.0f / sum;
    }
    __syncthreads();

    float o[8][8];
#pragma unroll
    for (int i = 0; i < 8; i++)
#pragma unroll
        for (int j = 0; j < 8; j++) o[i][j] = 0.f;

#pragma unroll 4
    for (int j = 0; j < 64; j++) {
        float p[8], b[8];
#pragma unroll
        for (int i = 0; i < 8; i++) p[i] = St[j * 64 + rr + i];
        *(float4*)(b)     = *(const float4*)&vs[j * 64 + cc];
        *(float4*)(b + 4) = *(const float4*)&vs[j * 64 + cc + 4];
#pragma unroll
        for (int i = 0; i < 8; i++)
#pragma unroll
            for (int jj = 0; jj < 8; jj++)
                o[i][jj] += p[i] * b[jj];
    }

#pragma unroll
    for (int i = 0; i < 8; i++) {
        float sc = inv[rr + i];
        float* op = out + ((long long)wb * WINW + rr + i) * C_DIM + h * HD + cc;
        float4 t0, t1;
        t0.x = o[i][0] * sc; t0.y = o[i][1] * sc;
        t0.z = o[i][2] * sc; t0.w = o[i][3] * sc;
        t1.x = o[i][4] * sc; t1.y = o[i][5] * sc;
        t1.z = o[i][6] * sc; t1.w = o[i][7] * sc;
        *(float4*)(op)     = t0;
        *(float4*)(op + 4) = t1;
    }
}

// ---------------------------------------------------------------------------
extern "C" void kernel_launch(void* const* d_in, const int* in_sizes, int n_in,
                              void* d_out, int out_size)
{
    const float* x      = (const float*)d_in[0];
    const float* qkv_w  = (const float*)d_in[1];
    const float* proj_w = (const float*)d_in[2];
    const float* proj_b = (const float*)d_in[3];
    float* out = (float*)d_out;

    float* qkv_buf = nullptr;
    float* att_buf = nullptr;
    cudaGetSymbolAddress((void**)&qkv_buf, g_qkv);
    cudaGetSymbolAddress((void**)&att_buf, g_att);

    const int gemm_smem = 4 * TB;                 // 64 KB
    cudaFuncSetAttribute(gemm_hmma, cudaFuncAttributeMaxDynamicSharedMemorySize,
                         gemm_smem);
    cudaFuncSetAttribute(attn64, cudaFuncAttributeMaxDynamicSharedMemorySize,
                         12480 * (int)sizeof(float));

    // 1) QKV projection (HMMA tensor cores)
    gemm_hmma<<<dim3(QKV_DIM / 128, M_ROWS / 128), 256, gemm_smem>>>(
        x, qkv_w, nullptr, qkv_buf, M_ROWS, QKV_DIM, C_DIM);

    // 2) Windowed attention
    attn64<<<dim3(NH, NWIN), 64, 12480 * sizeof(float)>>>(qkv_buf, att_buf);

    // 3) Output projection (HMMA tensor cores, +bias)
    gemm_hmma<<<dim3(C_DIM / 128, M_ROWS / 128), 256, gemm_smem>>>(
        att_buf, proj_w, proj_b, out, M_ROWS, C_DIM, C_DIM);
}

// round 4
// speedup vs baseline: 2.3601x; 1.1730x over previous
#include <cuda_runtime.h>
#include <cuda_bf16.h>
#include <cstdint>

// ---------------------------------------------------------------------------
// x[65536,512] -> qkv = x @ qkv_w^T -> windowed attn (1024x8, 64x64x64)
//   -> out = att @ proj_w^T + b
// GEMMs: HMMA bf16 with 3-term hi/lo split. Inputs preconverted to bf16 hi/lo
// in DRAM; GEMM fills smem with cp.async.cg (no in-loop conversion).
// ---------------------------------------------------------------------------

#define M_ROWS   65536
#define C_DIM    512
#define QKV_DIM  1536
#define NH       8
#define HD       64
#define WINW     64
#define NWIN     1024

__device__ float         g_qkv[(long long)M_ROWS * QKV_DIM];   // 402 MB fp32
__device__ __nv_bfloat16 g_xh [(long long)M_ROWS * C_DIM];     // 67 MB
__device__ __nv_bfloat16 g_xl [(long long)M_ROWS * C_DIM];
__device__ __nv_bfloat16 g_ath[(long long)M_ROWS * C_DIM];     // attn out hi
__device__ __nv_bfloat16 g_atl[(long long)M_ROWS * C_DIM];     // attn out lo
__device__ __nv_bfloat16 g_wqh[QKV_DIM * C_DIM];
__device__ __nv_bfloat16 g_wql[QKV_DIM * C_DIM];
__device__ __nv_bfloat16 g_wph[C_DIM * C_DIM];
__device__ __nv_bfloat16 g_wpl[C_DIM * C_DIM];

// ------------------------------ helpers ------------------------------------
__device__ __forceinline__ uint32_t smem_u32(const void* p) {
    uint32_t a;
    asm("{ .reg .u64 t; cvta.to.shared.u64 t, %1; cvt.u32.u64 %0, t; }"
        : "=r"(a) : "l"(p));
    return a;
}
__device__ __forceinline__ void ldsm4(uint32_t addr, uint32_t r[4]) {
    asm volatile("ldmatrix.sync.aligned.m8n8.x4.shared.b16 {%0,%1,%2,%3}, [%4];"
                 : "=r"(r[0]), "=r"(r[1]), "=r"(r[2]), "=r"(r[3]) : "r"(addr));
}
__device__ __forceinline__ void mma16816(float d[4], const uint32_t a[4],
                                         const uint32_t b0, const uint32_t b1) {
    asm volatile(
        "mma.sync.aligned.m16n8k16.row.col.f32.bf16.bf16.f32 "
        "{%0,%1,%2,%3},{%4,%5,%6,%7},{%8,%9},{%0,%1,%2,%3};"
        : "+f"(d[0]), "+f"(d[1]), "+f"(d[2]), "+f"(d[3])
        : "r"(a[0]), "r"(a[1]), "r"(a[2]), "r"(a[3]), "r"(b0), "r"(b1));
}
__device__ __forceinline__ void cp16(uint32_t saddr, const void* gaddr) {
    asm volatile("cp.async.cg.shared.global [%0], [%1], 16;"
                 :: "r"(saddr), "l"(gaddr));
}
#define CP_COMMIT() asm volatile("cp.async.commit_group;" ::: "memory")
#define CP_WAIT0()  asm volatile("cp.async.wait_group 0;" ::: "memory")

__device__ __forceinline__ uint32_t pack2(__nv_bfloat16 a, __nv_bfloat16 b) {
    return ((uint32_t)__bfloat16_as_ushort(b) << 16) | __bfloat16_as_ushort(a);
}
__device__ __forceinline__ void split1(float v, __nv_bfloat16& h, __nv_bfloat16& l) {
    h = __float2bfloat16(v);
    l = __float2bfloat16(v - __bfloat162float(h));
}

// ---------------------------------------------------------------------------
// Split pass: fp32 [n] -> bf16 hi[n] + lo[n]  (grid-stride, float4)
// ---------------------------------------------------------------------------
__global__ void split_f32(const float* __restrict__ src,
                          __nv_bfloat16* __restrict__ hi,
                          __nv_bfloat16* __restrict__ lo, long long n)
{
    long long i = ((long long)blockIdx.x * blockDim.x + threadIdx.x) * 8;
    if (i >= n) return;
    float4 v0 = *(const float4*)(src + i);
    float4 v1 = *(const float4*)(src + i + 4);
    float f[8] = {v0.x, v0.y, v0.z, v0.w, v1.x, v1.y, v1.z, v1.w};
    uint32_t H[4], L[4];
#pragma unroll
    for (int j = 0; j < 4; j++) {
        __nv_bfloat16 h0, h1, l0, l1;
        split1(f[2 * j], h0, l0);
        split1(f[2 * j + 1], h1, l1);
        H[j] = pack2(h0, h1);
        L[j] = pack2(l0, l1);
    }
    *(uint4*)(hi + i) = make_uint4(H[0], H[1], H[2], H[3]);
    *(uint4*)(lo + i) = make_uint4(L[0], L[1], L[2], L[3]);
}

// ---------------------------------------------------------------------------
// HMMA GEMM (NT) on preconverted bf16 hi/lo: C = A*B^T (+bias), fp32 out.
// CTA 128x128, BK=64. smem: 4 tiles (Ah,Al,Bh,Bl) of 128 rows x 128B, xor
// swizzle per 16B chunk. Fill via cp.async.cg. 8 warps = 4(M) x 2(N).
// ---------------------------------------------------------------------------
#define TB 16384

__global__ __launch_bounds__(256, 2)
void gemm_split(const __nv_bfloat16* __restrict__ Ah,
                const __nv_bfloat16* __restrict__ Al,
                const __nv_bfloat16* __restrict__ Bh,
                const __nv_bfloat16* __restrict__ Bl,
                const float* __restrict__ bias, float* __restrict__ C,
                int M, int N, int K)
{
    extern __shared__ char sm[];
    const uint32_t sb = smem_u32(sm);

    const int tid  = threadIdx.x;
    const int lane = tid & 31;
    const int wid  = tid >> 5;
    const int wm   = wid & 3;
    const int wn   = wid >> 2;
    const long long m0 = (long long)blockIdx.y * 128;
    const int n0 = blockIdx.x * 128;

    float acc[2][8][4];
#pragma unroll
    for (int i = 0; i < 2; i++)
#pragma unroll
        for (int j = 0; j < 8; j++)
#pragma unroll
            for (int l = 0; l < 4; l++) acc[i][j][l] = 0.f;

    const int arow0 = wm * 32 + (lane & 7) + ((lane >> 3) & 1) * 8;
    const int ac    = lane >> 4;
    const int brow0 = wn * 64 + (lane & 7) + (lane >> 4) * 8;
    const int bc    = (lane >> 3) & 1;

    // fill indices: 4 iterations x 256 threads = 1024 (row, chunk) slots/array
    const int frow = tid >> 3;          // advances by 32 per iter
    const int fc   = tid & 7;

    const int NCH = K >> 6;
    for (int ch = 0; ch < NCH; ch++) {
        __syncthreads();
#pragma unroll
        for (int i = 0; i < 4; i++) {
            int row = frow + i * 32;
            uint32_t off = (uint32_t)(row * 128 + ((fc ^ (row & 7)) << 4));
            long long ga = (m0 + row) * K + ch * 64 + fc * 8;
            long long gb = (long long)(n0 + row) * K + ch * 64 + fc * 8;
            cp16(sb + off,          Ah + ga);
            cp16(sb + TB + off,     Al + ga);
            cp16(sb + 2 * TB + off, Bh + gb);
            cp16(sb + 3 * TB + off, Bl + gb);
        }
        CP_COMMIT();
        CP_WAIT0();
        __syncthreads();

#pragma unroll
        for (int kk = 0; kk < 4; kk++) {
            uint32_t ah[2][4], al[2][4];
#pragma unroll
            for (int mt = 0; mt < 2; mt++) {
                int r = arow0 + mt * 16;
                uint32_t off = (uint32_t)(r * 128 + (((2 * kk + ac) ^ (r & 7)) << 4));
                ldsm4(sb + off, ah[mt]);
                ldsm4(sb + TB + off, al[mt]);
            }
#pragma unroll
            for (int nt = 0; nt < 4; nt++) {
                int r = brow0 + nt * 16;
                uint32_t off = (uint32_t)(r * 128 + (((2 * kk + bc) ^ (r & 7)) << 4));
                uint32_t bh[4], bl[4];
                ldsm4(sb + 2 * TB + off, bh);
                ldsm4(sb + 3 * TB + off, bl);
#pragma unroll
                for (int mt = 0; mt < 2; mt++) {
                    mma16816(acc[mt][nt * 2],     ah[mt], bh[0], bh[1]);
                    mma16816(acc[mt][nt * 2 + 1], ah[mt], bh[2], bh[3]);
                    mma16816(acc[mt][nt * 2],     ah[mt], bl[0], bl[1]);
                    mma16816(acc[mt][nt * 2 + 1], ah[mt], bl[2], bl[3]);
                    mma16816(acc[mt][nt * 2],     al[mt], bh[0], bh[1]);
                    mma16816(acc[mt][nt * 2 + 1], al[mt], bh[2], bh[3]);
                }
            }
        }
    }

    const int erow = lane >> 2;
    const int ecol = (lane & 3) * 2;
#pragma unroll
    for (int mt = 0; mt < 2; mt++) {
#pragma unroll
        for (int nt8 = 0; nt8 < 8; nt8++) {
            long long row = m0 + wm * 32 + mt * 16 + erow;
            int col = n0 + wn * 64 + nt8 * 8 + ecol;
            float b0 = bias ? bias[col]     : 0.f;
            float b1 = bias ? bias[col + 1] : 0.f;
            float2 r0 = make_float2(acc[mt][nt8][0] + b0, acc[mt][nt8][1] + b1);
            float2 r1 = make_float2(acc[mt][nt8][2] + b0, acc[mt][nt8][3] + b1);
            *(float2*)(C + row * N + col)       = r0;
            *(float2*)(C + (row + 8) * N + col) = r1;
        }
    }
}

// ---------------------------------------------------------------------------
// Windowed attention: one CTA per (window, head). fp32 math; epilogue emits
// bf16 hi/lo split directly (input to the projection GEMM).
// ---------------------------------------------------------------------------
__global__ __launch_bounds__(64)
void attn64(const float* __restrict__ qkv,
            __nv_bfloat16* __restrict__ oh, __nv_bfloat16* __restrict__ ol)
{
    extern __shared__ float smf[];
    float* qt  = smf;
    float* kt  = smf + 4160;
    float* vs  = smf + 8320;
    float* inv = smf + 12416;

    const int tid = threadIdx.x;
    const int h  = blockIdx.x;
    const int wb = blockIdx.y;

    const float* base = qkv + (long long)wb * WINW * QKV_DIM + h * HD;

    for (int idx = tid; idx < 1024; idx += 64) {
        int w = idx >> 4;
        int e = (idx & 15) << 2;
        const float* p = base + (long long)w * QKV_DIM + e;
        float4 q4 = *(const float4*)(p);
        float4 k4 = *(const float4*)(p + 512);
        float4 v4 = *(const float4*)(p + 1024);
        qt[(e + 0) * 65 + w] = q4.x; qt[(e + 1) * 65 + w] = q4.y;
        qt[(e + 2) * 65 + w] = q4.z; qt[(e + 3) * 65 + w] = q4.w;
        kt[(e + 0) * 65 + w] = k4.x; kt[(e + 1) * 65 + w] = k4.y;
        kt[(e + 2) * 65 + w] = k4.z; kt[(e + 3) * 65 + w] = k4.w;
        *(float4*)&vs[w * 64 + e] = v4;
    }
    __syncthreads();

    const int rr = (tid >> 3) << 3;
    const int cc = (tid & 7) << 3;

    float s[8][8];
#pragma unroll
    for (int i = 0; i < 8; i++)
#pragma unroll
        for (int j = 0; j < 8; j++) s[i][j] = 0.f;

#pragma unroll 4
    for (int e = 0; e < 64; e++) {
        float a[8], b[8];
#pragma unroll
        for (int i = 0; i < 8; i++) a[i] = qt[e * 65 + rr + i];
#pragma unroll
        for (int j = 0; j < 8; j++) b[j] = kt[e * 65 + cc + j];
#pragma unroll
        for (int i = 0; i < 8; i++)
#pragma unroll
            for (int j = 0; j < 8; j++)
                s[i][j] += a[i] * b[j];
    }
    __syncthreads();

    float* St = qt;
#pragma unroll
    for (int i = 0; i < 8; i++)
#pragma unroll
        for (int j = 0; j < 8; j++)
            St[(cc + j) * 64 + rr + i] = s[i][j] * 0.125f;
    __syncthreads();

    {
        int r = tid;
        float mx = -1e30f;
#pragma unroll 8
        for (int j = 0; j < 64; j++) mx = fmaxf(mx, St[j * 64 + r]);
        float sum = 0.f;
#pragma unroll 8
        for (int j = 0; j < 64; j++) {
            float p = __expf(St[j * 64 + r] - mx);
            St[j * 64 + r] = p;
            sum += p;
        }
        inv[r] = 1.0f / sum;
    }
    __syncthreads();

    float o[8][8];
#pragma unroll
    for (int i = 0; i < 8; i++)
#pragma unroll
        for (int j = 0; j < 8; j++) o[i][j] = 0.f;

#pragma unroll 4
    for (int j = 0; j < 64; j++) {
        float p[8], b[8];
#pragma unroll
        for (int i = 0; i < 8; i++) p[i] = St[j * 64 + rr + i];
        *(float4*)(b)     = *(const float4*)&vs[j * 64 + cc];
        *(float4*)(b + 4) = *(const float4*)&vs[j * 64 + cc + 4];
#pragma unroll
        for (int i = 0; i < 8; i++)
#pragma unroll
            for (int jj = 0; jj < 8; jj++)
                o[i][jj] += p[i] * b[jj];
    }

#pragma unroll
    for (int i = 0; i < 8; i++) {
        float sc = inv[rr + i];
        long long pos = ((long long)wb * WINW + rr + i) * C_DIM + h * HD + cc;
        uint32_t H[4], L[4];
#pragma unroll
        for (int j = 0; j < 4; j++) {
            __nv_bfloat16 h0, h1, l0, l1;
            split1(o[i][2 * j] * sc, h0, l0);
            split1(o[i][2 * j + 1] * sc, h1, l1);
            H[j] = pack2(h0, h1);
            L[j] = pack2(l0, l1);
        }
        *(uint4*)(oh + pos) = make_uint4(H[0], H[1], H[2], H[3]);
        *(uint4*)(ol + pos) = make_uint4(L[0], L[1], L[2], L[3]);
    }
}

// ---------------------------------------------------------------------------
extern "C" void kernel_launch(void* const* d_in, const int* in_sizes, int n_in,
                              void* d_out, int out_size)
{
    const float* x      = (const float*)d_in[0];
    const float* qkv_w  = (const float*)d_in[1];
    const float* proj_w = (const float*)d_in[2];
    const float* proj_b = (const float*)d_in[3];
    float* out = (float*)d_out;

    float *qkv_buf = nullptr;
    __nv_bfloat16 *xh, *xl, *ath, *atl, *wqh, *wql, *wph, *wpl;
    cudaGetSymbolAddress((void**)&qkv_buf, g_qkv);
    cudaGetSymbolAddress((void**)&xh,  g_xh);
    cudaGetSymbolAddress((void**)&xl,  g_xl);
    cudaGetSymbolAddress((void**)&ath, g_ath);
    cudaGetSymbolAddress((void**)&atl, g_atl);
    cudaGetSymbolAddress((void**)&wqh, g_wqh);
    cudaGetSymbolAddress((void**)&wql, g_wql);
    cudaGetSymbolAddress((void**)&wph, g_wph);
    cudaGetSymbolAddress((void**)&wpl, g_wpl);

    const int gemm_smem = 4 * TB;     // 64 KB
    cudaFuncSetAttribute(gemm_split, cudaFuncAttributeMaxDynamicSharedMemorySize,
                         gemm_smem);
    cudaFuncSetAttribute(attn64, cudaFuncAttributeMaxDynamicSharedMemorySize,
                         12480 * (int)sizeof(float));

    // 0) split inputs to bf16 hi/lo
    {
        long long nx = (long long)M_ROWS * C_DIM;
        split_f32<<<(unsigned)((nx / 8 + 255) / 256), 256>>>(x, xh, xl, nx);
        long long nq = (long long)QKV_DIM * C_DIM;
        split_f32<<<(unsigned)((nq / 8 + 255) / 256), 256>>>(qkv_w, wqh, wql, nq);
        long long np = (long long)C_DIM * C_DIM;
        split_f32<<<(unsigned)((np / 8 + 255) / 256), 256>>>(proj_w, wph, wpl, np);
    }

    // 1) QKV projection
    gemm_split<<<dim3(QKV_DIM / 128, M_ROWS / 128), 256, gemm_smem>>>(
        xh, xl, wqh, wql, nullptr, qkv_buf, M_ROWS, QKV_DIM, C_DIM);

    // 2) Windowed attention (emits bf16 hi/lo)
    attn64<<<dim3(NH, NWIN), 64, 12480 * sizeof(float)>>>(qkv_buf, ath, atl);

    // 3) Output projection (+bias)
    gemm_split<<<dim3(C_DIM / 128, M_ROWS / 128), 256, gemm_smem>>>(
        ath, atl, wph, wpl, proj_b, out, M_ROWS, C_DIM, C_DIM);
}